// round 5
// baseline (speedup 1.0000x reference)
#include <cuda_runtime.h>
#include <cuda_bf16.h>
#include <cstdint>

#define N_NODES_MAX 100000
#define DSIGMA_DT (-0.0001f)
#define PHI_THRESH 0.3f
#define EPS 1e-8f

// Packed {pos.xyz, T} per node; 2-replica accumulator {num.xyz, cnt}.
__device__ float4 g_packed[N_NODES_MAX];
__device__ float4 g_acc[2][N_NODES_MAX];
__device__ int g_idx_is64;

// Sense-reversing grid barrier state. Replay-safe: ctr always returns to 0,
// gen is monotonic (spinners compare against their snapshot).
__device__ unsigned g_bar_ctr = 0;
__device__ unsigned g_bar_gen = 0;

__device__ __forceinline__ void grid_barrier(unsigned nblocks) {
    __syncthreads();
    if (threadIdx.x == 0) {
        volatile unsigned* genp = &g_bar_gen;
        unsigned gen = *genp;          // snapshot BEFORE arriving
        __threadfence();               // publish this block's phase writes
        if (atomicAdd(&g_bar_ctr, 1u) == nblocks - 1u) {
            g_bar_ctr = 0;
            __threadfence();
            atomicAdd(&g_bar_gen, 1u); // release
        } else {
            while (*genp == gen) { __nanosleep(64); }
        }
        __threadfence();               // acquire
    }
    __syncthreads();
}

__global__ __launch_bounds__(256) void fused_kernel(
        const float* __restrict__ x,
        const float* __restrict__ pos,
        const void* __restrict__ edge_index,
        float* __restrict__ out,
        int n_nodes, int n_edges, unsigned nblocks) {
    const int tid = blockIdx.x * blockDim.x + threadIdx.x;
    const int nthreads = gridDim.x * blockDim.x;

    // ── Phase A: pack {pos, T}, zero accumulators, detect index dtype ──
    for (int i = tid; i < n_nodes; i += nthreads) {
        float p0 = pos[i * 3 + 0];
        float p1 = pos[i * 3 + 1];
        float p2 = pos[i * 3 + 2];
        float t  = __ldg(&x[i * 9 + 3]);
        g_packed[i] = make_float4(p0, p1, p2, t);
        g_acc[0][i] = make_float4(0.f, 0.f, 0.f, 0.f);
        g_acc[1][i] = make_float4(0.f, 0.f, 0.f, 0.f);
    }
    if (tid == 0) {
        // int64 little-endian with values < 2^31 => odd 32-bit words all zero.
        const unsigned int* w = (const unsigned int*)edge_index;
        unsigned int acc = 0;
        #pragma unroll
        for (int k = 0; k < 64; k++) acc |= w[2 * k + 1];
        g_idx_is64 = (acc == 0) ? 1 : 0;
    }

    grid_barrier(nblocks);

    // ── Phase B: per-edge scatter, one RED.v4.f32 per edge, 2 replicas ──
    const int is64 = g_idx_is64;
    if (is64) {
        const long long* ei = (const long long*)edge_index;
        for (int e = tid; e < n_edges; e += nthreads) {
            int s = (int)__ldcs(&ei[e]);
            int d = (int)__ldcs(&ei[n_edges + e]);
            float4 a = __ldg(&g_packed[s]);
            float4 b = __ldg(&g_packed[d]);
            float dT = a.w - b.w;
            float px = a.x - b.x, py = a.y - b.y, pz = a.z - b.z;
            float w = dT / (px * px + py * py + pz * pz + EPS);
            float4* addr = &g_acc[e & 1][d];
            asm volatile("red.global.add.v4.f32 [%0], {%1, %2, %3, %4};"
                         :: "l"(addr), "f"(w * px), "f"(w * py), "f"(w * pz), "f"(1.0f)
                         : "memory");
        }
    } else {
        const int* ei = (const int*)edge_index;
        for (int e = tid; e < n_edges; e += nthreads) {
            int s = __ldcs(&ei[e]);
            int d = __ldcs(&ei[n_edges + e]);
            float4 a = __ldg(&g_packed[s]);
            float4 b = __ldg(&g_packed[d]);
            float dT = a.w - b.w;
            float px = a.x - b.x, py = a.y - b.y, pz = a.z - b.z;
            float w = dT / (px * px + py * py + pz * pz + EPS);
            float4* addr = &g_acc[e & 1][d];
            asm volatile("red.global.add.v4.f32 [%0], {%1, %2, %3, %4};"
                         :: "l"(addr), "f"(w * px), "f"(w * py), "f"(w * pz), "f"(1.0f)
                         : "memory");
        }
    }

    grid_barrier(nblocks);

    // ── Phase C: finalize ──
    for (int i = tid; i < n_nodes; i += nthreads) {
        float4 a0 = g_acc[0][i];
        float4 a1 = g_acc[1][i];
        float phi = __ldg(&x[i * 9 + 8]);
        float nx = a0.x + a1.x, ny = a0.y + a1.y, nz = a0.z + a1.z;
        float cnt = fmaxf(a0.w + a1.w, 1.0f);
        float mask = (fabsf(phi) < PHI_THRESH) ? 1.0f : 0.0f;
        float s = DSIGMA_DT * mask / cnt;
        out[i * 3 + 0] = s * nx;
        out[i * 3 + 1] = s * ny;
        out[i * 3 + 2] = s * nz;
    }
}

extern "C" void kernel_launch(void* const* d_in, const int* in_sizes, int n_in,
                              void* d_out, int out_size) {
    const float* x = (const float*)d_in[0];    // [N, 9]
    const float* pos = (const float*)d_in[1];  // [N, 3]
    const void* edge_index = d_in[2];          // [2, E] int32 or int64

    int n_nodes = in_sizes[1] / 3;
    int n_edges = in_sizes[2] / 2;
    float* out = (float*)d_out;

    // Size grid so every block is resident -> spin barrier cannot deadlock.
    int dev = 0;
    cudaGetDevice(&dev);
    int sms = 0;
    cudaDeviceGetAttribute(&sms, cudaDevAttrMultiProcessorCount, dev);
    int blocks_per_sm = 0;
    cudaOccupancyMaxActiveBlocksPerMultiprocessor(&blocks_per_sm, fused_kernel, 256, 0);
    if (blocks_per_sm < 1) blocks_per_sm = 1;
    unsigned nblocks = (unsigned)(sms * blocks_per_sm);

    fused_kernel<<<nblocks, 256>>>(x, pos, edge_index, out,
                                   n_nodes, n_edges, nblocks);
}

// round 6
// speedup vs baseline: 1.1088x; 1.1088x over previous
#include <cuda_runtime.h>
#include <cuda_bf16.h>
#include <cstdint>

#define N_NODES_MAX 100000
#define DSIGMA_DT (-0.0001f)
#define PHI_THRESH 0.3f
#define EPS 1e-8f

// Packed {pos.x, pos.y, pos.z, T} per node; accumulator {num.xyz, cnt}.
__device__ float4 g_packed[N_NODES_MAX];
__device__ float4 g_acc[N_NODES_MAX];
__device__ int g_idx_is64;

// 4 threads per node: component c<3 -> pos, c==3 -> T. Each thread does one
// 4B load + two coalesced 4B stores (pack + acc zero). 4x the thread-level
// parallelism of the old per-node prep -> bandwidth-bound instead of
// latency-bound on cold DRAM reads.
__global__ __launch_bounds__(256) void prep_kernel(
        const float* __restrict__ x,
        const float* __restrict__ pos,
        const unsigned int* __restrict__ ei_words,
        int n_nodes) {
    int t = blockIdx.x * blockDim.x + threadIdx.x;
    int total = n_nodes * 4;
    if (t < total) {
        int i = t >> 2;
        int c = t & 3;
        float v = (c < 3) ? __ldg(&pos[i * 3 + c]) : __ldg(&x[i * 9 + 3]);
        ((float*)g_packed)[t] = v;
        ((float*)g_acc)[t] = 0.0f;
    }
    if (t == 0) {
        // int64 little-endian with values < 2^31 => odd 32-bit words all zero.
        unsigned int acc = 0;
        #pragma unroll
        for (int k = 0; k < 64; k++) acc |= ei_words[2 * k + 1];
        g_idx_is64 = (acc == 0) ? 1 : 0;
    }
}

// One edge per thread; 2 LDG.128 gathers + 1 RED.v4.f32 (wavefront floor).
__global__ __launch_bounds__(256) void edge_scatter_kernel(
        const void* __restrict__ edge_index, int n_edges) {
    int e = blockIdx.x * blockDim.x + threadIdx.x;
    if (e >= n_edges) return;

    int src, dst;
    if (g_idx_is64) {
        const long long* ei = (const long long*)edge_index;
        src = (int)ei[e];
        dst = (int)ei[n_edges + e];
    } else {
        const int* ei = (const int*)edge_index;
        src = ei[e];
        dst = ei[n_edges + e];
    }

    float4 a = __ldg(&g_packed[src]);
    float4 b = __ldg(&g_packed[dst]);

    float dT = a.w - b.w;
    float px = a.x - b.x;
    float py = a.y - b.y;
    float pz = a.z - b.z;

    float dist2 = px * px + py * py + pz * pz + EPS;
    float w = dT / dist2;

    float4* addr = &g_acc[dst];
    asm volatile("red.global.add.v4.f32 [%0], {%1, %2, %3, %4};"
                 :: "l"(addr), "f"(w * px), "f"(w * py), "f"(w * pz), "f"(1.0f)
                 : "memory");
}

__global__ __launch_bounds__(256) void finalize_kernel(
        const float* __restrict__ x,
        float* __restrict__ out,
        int n_nodes) {
    int i = blockIdx.x * blockDim.x + threadIdx.x;
    if (i >= n_nodes) return;

    float4 a = g_acc[i];
    float phi = __ldg(&x[i * 9 + 8]);

    float cnt = fmaxf(a.w, 1.0f);
    float mask = (fabsf(phi) < PHI_THRESH) ? 1.0f : 0.0f;
    float s = DSIGMA_DT * mask / cnt;

    out[i * 3 + 0] = s * a.x;
    out[i * 3 + 1] = s * a.y;
    out[i * 3 + 2] = s * a.z;
}

extern "C" void kernel_launch(void* const* d_in, const int* in_sizes, int n_in,
                              void* d_out, int out_size) {
    const float* x = (const float*)d_in[0];    // [N, 9]
    const float* pos = (const float*)d_in[1];  // [N, 3]
    const void* edge_index = d_in[2];          // [2, E] int32 or int64

    int n_nodes = in_sizes[1] / 3;
    int n_edges = in_sizes[2] / 2;
    float* out = (float*)d_out;

    const int TPB = 256;
    prep_kernel<<<(n_nodes * 4 + TPB - 1) / TPB, TPB>>>(
        x, pos, (const unsigned int*)edge_index, n_nodes);
    edge_scatter_kernel<<<(n_edges + TPB - 1) / TPB, TPB>>>(edge_index, n_edges);
    finalize_kernel<<<(n_nodes + TPB - 1) / TPB, TPB>>>(x, out, n_nodes);
}

// round 7
// speedup vs baseline: 1.1316x; 1.0206x over previous
#include <cuda_runtime.h>
#include <cuda_bf16.h>
#include <cstdint>

#define N_NODES_MAX 100000
#define DSIGMA_DT (-0.0001f)
#define PHI_THRESH 0.3f
#define EPS 1e-8f

// Packed {pos.x, pos.y, pos.z, T} per node; accumulator {num.xyz, cnt}.
__device__ float4 g_packed[N_NODES_MAX];
__device__ float4 g_acc[N_NODES_MAX];
__device__ int g_idx_is64;

// Region A (t < nx4): sequential float4 scan of x; lanes scatter T (col 3)
//   into g_packed[node].w. Streams x at full DRAM bandwidth instead of
//   fetching 100k isolated 32B sectors; also warms phi sectors for finalize.
// Region B: per-node pos pack (dense 12B-stride reads) + acc zeroing.
__global__ __launch_bounds__(256) void prep_kernel(
        const float* __restrict__ x,
        const float* __restrict__ pos,
        const unsigned int* __restrict__ ei_words,
        int n_nodes) {
    int t = blockIdx.x * blockDim.x + threadIdx.x;
    int nxf = n_nodes * 9;
    int nx4 = nxf >> 2;

    if (t < nx4) {
        float4 v = __ldg(((const float4*)x) + t);
        int g = t << 2;
        #pragma unroll
        for (int k = 0; k < 4; k++) {
            int gi = g + k;
            int node = gi / 9;
            int c = gi - node * 9;
            if (c == 3) {
                float val = (k == 0) ? v.x : (k == 1) ? v.y : (k == 2) ? v.z : v.w;
                ((float*)g_packed)[node * 4 + 3] = val;
            }
        }
        if (t == 0) {
            // Scalar tail of the x scan (if nxf % 4 != 0).
            for (int gi = nx4 << 2; gi < nxf; gi++) {
                int node = gi / 9;
                int c = gi - node * 9;
                if (c == 3) ((float*)g_packed)[node * 4 + 3] = __ldg(&x[gi]);
            }
            // int64 little-endian with values < 2^31 => odd 32-bit words zero.
            unsigned int acc = 0;
            #pragma unroll
            for (int kk = 0; kk < 64; kk++) acc |= ei_words[2 * kk + 1];
            g_idx_is64 = (acc == 0) ? 1 : 0;
        }
    } else if (t < nx4 + n_nodes) {
        int i = t - nx4;
        float p0 = __ldg(&pos[i * 3 + 0]);
        float p1 = __ldg(&pos[i * 3 + 1]);
        float p2 = __ldg(&pos[i * 3 + 2]);
        ((float*)g_packed)[i * 4 + 0] = p0;
        ((float*)g_packed)[i * 4 + 1] = p1;
        ((float*)g_packed)[i * 4 + 2] = p2;
        g_acc[i] = make_float4(0.f, 0.f, 0.f, 0.f);
    }
}

// One edge per thread; 2 LDG.128 gathers + 1 RED.v4.f32 (wavefront floor).
// __ldcs on the 51MB index stream: evict-first, protects the hot node
// tables (and the x sectors finalize needs) in L2.
__global__ __launch_bounds__(256) void edge_scatter_kernel(
        const void* __restrict__ edge_index, int n_edges) {
    int e = blockIdx.x * blockDim.x + threadIdx.x;
    if (e >= n_edges) return;

    int src, dst;
    if (g_idx_is64) {
        const long long* ei = (const long long*)edge_index;
        src = (int)__ldcs(&ei[e]);
        dst = (int)__ldcs(&ei[n_edges + e]);
    } else {
        const int* ei = (const int*)edge_index;
        src = __ldcs(&ei[e]);
        dst = __ldcs(&ei[n_edges + e]);
    }

    float4 a = __ldg(&g_packed[src]);
    float4 b = __ldg(&g_packed[dst]);

    float dT = a.w - b.w;
    float px = a.x - b.x;
    float py = a.y - b.y;
    float pz = a.z - b.z;

    float dist2 = px * px + py * py + pz * pz + EPS;
    float w = dT / dist2;

    float4* addr = &g_acc[dst];
    asm volatile("red.global.add.v4.f32 [%0], {%1, %2, %3, %4};"
                 :: "l"(addr), "f"(w * px), "f"(w * py), "f"(w * pz), "f"(1.0f)
                 : "memory");
}

__global__ __launch_bounds__(256) void finalize_kernel(
        const float* __restrict__ x,
        float* __restrict__ out,
        int n_nodes) {
    int i = blockIdx.x * blockDim.x + threadIdx.x;
    if (i >= n_nodes) return;

    float4 a = g_acc[i];
    float phi = __ldg(&x[i * 9 + 8]);

    float cnt = fmaxf(a.w, 1.0f);
    float mask = (fabsf(phi) < PHI_THRESH) ? 1.0f : 0.0f;
    float s = DSIGMA_DT * mask / cnt;

    out[i * 3 + 0] = s * a.x;
    out[i * 3 + 1] = s * a.y;
    out[i * 3 + 2] = s * a.z;
}

extern "C" void kernel_launch(void* const* d_in, const int* in_sizes, int n_in,
                              void* d_out, int out_size) {
    const float* x = (const float*)d_in[0];    // [N, 9]
    const float* pos = (const float*)d_in[1];  // [N, 3]
    const void* edge_index = d_in[2];          // [2, E] int32 or int64

    int n_nodes = in_sizes[1] / 3;
    int n_edges = in_sizes[2] / 2;
    float* out = (float*)d_out;

    const int TPB = 256;
    int prep_threads = (n_nodes * 9) / 4 + n_nodes;
    prep_kernel<<<(prep_threads + TPB - 1) / TPB, TPB>>>(
        x, pos, (const unsigned int*)edge_index, n_nodes);
    edge_scatter_kernel<<<(n_edges + TPB - 1) / TPB, TPB>>>(edge_index, n_edges);
    finalize_kernel<<<(n_nodes + TPB - 1) / TPB, TPB>>>(x, out, n_nodes);
}

// round 8
// speedup vs baseline: 2.1986x; 1.9429x over previous
#include <cuda_runtime.h>
#include <cuda_bf16.h>
#include <cstdint>

#define N_NODES_MAX 100000
#define MASK_WORDS ((N_NODES_MAX + 31) / 32)
#define DSIGMA_DT (-0.0001f)
#define PHI_THRESH 0.3f
#define EPS 1e-8f

// Packed {pos.x, pos.y, pos.z, T} per node; accumulator {num.xyz, cnt};
// interface-mask bitmap (1 bit per node).
__device__ float4 g_packed[N_NODES_MAX];
__device__ float4 g_acc[N_NODES_MAX];
__device__ unsigned g_mask[MASK_WORDS];
__device__ int g_idx_is64;

// Per-node: pack {pos,T}, zero acc, build mask bitmap via ballot, detect dtype.
__global__ __launch_bounds__(256) void prep_kernel(
        const float* __restrict__ x,
        const float* __restrict__ pos,
        const unsigned int* __restrict__ ei_words,
        int n_nodes) {
    int i = blockIdx.x * blockDim.x + threadIdx.x;
    bool active = (i < n_nodes);

    unsigned bit = 0;
    if (active) {
        float p0 = __ldg(&pos[i * 3 + 0]);
        float p1 = __ldg(&pos[i * 3 + 1]);
        float p2 = __ldg(&pos[i * 3 + 2]);
        float t  = __ldg(&x[i * 9 + 3]);
        float phi = __ldg(&x[i * 9 + 8]);
        g_packed[i] = make_float4(p0, p1, p2, t);
        g_acc[i] = make_float4(0.f, 0.f, 0.f, 0.f);
        bit = (fabsf(phi) < PHI_THRESH) ? 1u : 0u;
    }
    // Full-warp ballot: inactive lanes contribute 0. No atomics, no zeroing.
    unsigned word = __ballot_sync(0xFFFFFFFFu, bit);
    if ((threadIdx.x & 31) == 0 && (i >> 5) < MASK_WORDS && (i < n_nodes || word != 0 || (i - 31) < n_nodes)) {
        if ((i - (int)(threadIdx.x & 31)) < n_nodes)  // warp has at least one valid node
            g_mask[i >> 5] = word;
    }

    if (i == 0) {
        // int64 little-endian with values < 2^31 => odd 32-bit words all zero.
        unsigned int acc = 0;
        #pragma unroll
        for (int k = 0; k < 64; k++) acc |= ei_words[2 * k + 1];
        g_idx_is64 = (acc == 0) ? 1 : 0;
    }
}

// Grid-stride edge scatter with shared-memory mask bitmap.
// ~76% of edges have a masked-out dst and contribute exactly zero to the
// output -> skip their gathers and RED entirely.
__global__ __launch_bounds__(512) void edge_scatter_kernel(
        const void* __restrict__ edge_index, int n_edges, int mask_words) {
    __shared__ unsigned smask[MASK_WORDS];
    for (int w = threadIdx.x; w < mask_words; w += blockDim.x)
        smask[w] = g_mask[w];
    __syncthreads();

    const int stride = gridDim.x * blockDim.x;
    const int start = blockIdx.x * blockDim.x + threadIdx.x;
    const int is64 = g_idx_is64;

    if (is64) {
        const long long* ei = (const long long*)edge_index;
        for (int e = start; e < n_edges; e += stride) {
            int d = (int)__ldcs(&ei[n_edges + e]);
            if ((smask[d >> 5] >> (d & 31)) & 1u) {
                int s = (int)__ldcs(&ei[e]);
                float4 a = __ldg(&g_packed[s]);
                float4 b = __ldg(&g_packed[d]);
                float dT = a.w - b.w;
                float px = a.x - b.x, py = a.y - b.y, pz = a.z - b.z;
                float w = dT / (px * px + py * py + pz * pz + EPS);
                float4* addr = &g_acc[d];
                asm volatile("red.global.add.v4.f32 [%0], {%1, %2, %3, %4};"
                             :: "l"(addr), "f"(w * px), "f"(w * py), "f"(w * pz), "f"(1.0f)
                             : "memory");
            }
        }
    } else {
        const int* ei = (const int*)edge_index;
        for (int e = start; e < n_edges; e += stride) {
            int d = __ldcs(&ei[n_edges + e]);
            if ((smask[d >> 5] >> (d & 31)) & 1u) {
                int s = __ldcs(&ei[e]);
                float4 a = __ldg(&g_packed[s]);
                float4 b = __ldg(&g_packed[d]);
                float dT = a.w - b.w;
                float px = a.x - b.x, py = a.y - b.y, pz = a.z - b.z;
                float w = dT / (px * px + py * py + pz * pz + EPS);
                float4* addr = &g_acc[d];
                asm volatile("red.global.add.v4.f32 [%0], {%1, %2, %3, %4};"
                             :: "l"(addr), "f"(w * px), "f"(w * py), "f"(w * pz), "f"(1.0f)
                             : "memory");
            }
        }
    }
}

__global__ __launch_bounds__(256) void finalize_kernel(
        float* __restrict__ out, int n_nodes) {
    int i = blockIdx.x * blockDim.x + threadIdx.x;
    if (i >= n_nodes) return;

    unsigned bit = (g_mask[i >> 5] >> (i & 31)) & 1u;
    float4 a = g_acc[i];

    float cnt = fmaxf(a.w, 1.0f);
    float s = bit ? (DSIGMA_DT / cnt) : 0.0f;

    out[i * 3 + 0] = s * a.x;
    out[i * 3 + 1] = s * a.y;
    out[i * 3 + 2] = s * a.z;
}

extern "C" void kernel_launch(void* const* d_in, const int* in_sizes, int n_in,
                              void* d_out, int out_size) {
    const float* x = (const float*)d_in[0];    // [N, 9]
    const float* pos = (const float*)d_in[1];  // [N, 3]
    const void* edge_index = d_in[2];          // [2, E] int32 or int64

    int n_nodes = in_sizes[1] / 3;
    int n_edges = in_sizes[2] / 2;
    int mask_words = (n_nodes + 31) / 32;
    float* out = (float*)d_out;

    prep_kernel<<<(n_nodes + 255) / 256, 256>>>(
        x, pos, (const unsigned int*)edge_index, n_nodes);

    int eblocks = (n_edges + 511) / 512;
    if (eblocks > 592) eblocks = 592;   // ~4 blocks/SM, grid-stride
    edge_scatter_kernel<<<eblocks, 512>>>(edge_index, n_edges, mask_words);

    finalize_kernel<<<(n_nodes + 255) / 256, 256>>>(out, n_nodes);
}